// round 11
// baseline (speedup 1.0000x reference)
#include <cuda_runtime.h>
#include <cuda_bf16.h>

// Problem: ExpertChoiceRouter  B=8, S=8192, D=1024, KEEP_RATIO=0.5
// inputs: hidden_states f32 [B,S,D], active_mask bool->f32 [B,S],
//         scorer_w f32 [D], scorer_b f32 [1]
// output: keep_mask bool->f32 [B,S]   (write 1.0f / 0.0f)
//
// Evidence from R5: rel_err == 1.0 exactly => harness saw all-zero output
// => bool tensors are promoted to float32. Mask is read as 4-byte word != 0
// (correct for both f32 and i32 promotions); output written as f32.
//
// Kernel 1 (HBM-bound, 256 MB): key[b,s] = monotone-uint(score) if active else 0
// Kernel 2 (tiny, 8 blocks):    per-row radix-select k-th largest + stable ties

#define B_ 8
#define S_ 8192
#define D_ 1024
#define NTOK (B_ * S_)

// scratch for radix keys (no cudaMalloc allowed)
__device__ unsigned int g_keys[NTOK];

// ---------------------------------------------------------------------------
// Kernel 1: warp per token. key = flip(dot(hidden_row, w) + bias), masked.
// ---------------------------------------------------------------------------
__global__ __launch_bounds__(256) void score_kernel(
    const float* __restrict__ hidden,
    const unsigned int* __restrict__ active,   // 4-byte words; nonzero = active
    const float* __restrict__ w,
    const float* __restrict__ bias,
    unsigned int* __restrict__ keys)
{
    __shared__ float sw[D_];
    for (int i = threadIdx.x; i < D_; i += 256) sw[i] = w[i];
    __syncthreads();

    const int warp = threadIdx.x >> 5;
    const int lane = threadIdx.x & 31;
    const int token = blockIdx.x * 8 + warp;   // 8192 blocks * 8 warps = 65536

    const float4* __restrict__ row =
        reinterpret_cast<const float4*>(hidden + (size_t)token * D_);
    const float4* __restrict__ swv = reinterpret_cast<const float4*>(sw);

    float acc = 0.0f;
#pragma unroll
    for (int j = 0; j < 8; j++) {
        float4 v  = __ldcs(&row[lane + j * 32]);   // streaming: touched once
        float4 wv = swv[lane + j * 32];
        acc += v.x * wv.x + v.y * wv.y + v.z * wv.z + v.w * wv.w;
    }
#pragma unroll
    for (int o = 16; o; o >>= 1) acc += __shfl_xor_sync(0xffffffffu, acc, o);

    if (lane == 0) {
        float s = acc + bias[0];
        unsigned int u = __float_as_uint(s);
        // monotone map: larger float -> larger uint; finite active keys are > 0
        unsigned int kk = (u & 0x80000000u) ? ~u : (u | 0x80000000u);
        keys[token] = (active[token] != 0u) ? kk : 0u;
    }
}

// ---------------------------------------------------------------------------
// Kernel 2: per-row variable top-k (one 1024-thread block per row).
// k = max(1, ceil(n_active * 0.5)) = (n_active + 1) / 2   (n_active > 0)
// Tie-break: stable argsort => among equal scores, smaller index kept first.
// ---------------------------------------------------------------------------
__global__ __launch_bounds__(1024) void select_kernel(
    const unsigned int* __restrict__ keys,
    const unsigned int* __restrict__ active,   // 4-byte words; nonzero = active
    float* __restrict__ out)                   // f32 keep_mask: 1.0f / 0.0f
{
    __shared__ unsigned int key[S_];        // 32 KB
    __shared__ int hist[256];
    __shared__ int wsum[8];                 // per-warp bin-group totals
    __shared__ int wtot[32];
    __shared__ int s_nactive;
    __shared__ int s_sel, s_kk;

    const int tid  = threadIdx.x;
    const int lane = tid & 31;
    const int wid  = tid >> 5;
    const int row  = blockIdx.x;
    const unsigned int* rk = keys + row * S_;
    const unsigned int* ra = active + row * S_;
    float*              ro = out + row * S_;

    if (tid == 0) s_nactive = 0;
    __syncthreads();

    // load keys (uint4) into SMEM; count active words
    {
        const uint4* rk4 = reinterpret_cast<const uint4*>(rk);
        uint4* key4 = reinterpret_cast<uint4*>(key);
        for (int i = tid; i < S_ / 4; i += 1024) key4[i] = rk4[i];
    }
    int my_active = 0;
    {
        const uint4* ra4 = reinterpret_cast<const uint4*>(ra);
        for (int i = tid; i < S_ / 4; i += 1024) {
            uint4 m = ra4[i];
            my_active += (m.x != 0u) + (m.y != 0u) + (m.z != 0u) + (m.w != 0u);
        }
    }
#pragma unroll
    for (int o = 16; o; o >>= 1) my_active += __shfl_xor_sync(0xffffffffu, my_active, o);
    if (lane == 0) atomicAdd(&s_nactive, my_active);
    __syncthreads();

    const int n_active = s_nactive;
    if (n_active == 0) {
        for (int i = tid; i < S_; i += 1024) ro[i] = 0.0f;
        return;
    }
    const int k = (n_active + 1) >> 1;        // ceil(n/2), >= 1, <= n_active

    // ---- 4-pass MSB radix select for the k-th largest key ----
    unsigned int prefix = 0, pmask = 0;
    int kk_rem = k;
#pragma unroll
    for (int shift = 24; shift >= 0; shift -= 8) {
        if (tid < 256) hist[tid] = 0;
        __syncthreads();

        // warp-aggregated histogram: N(0,1) scores cluster into few exponent
        // bytes; collapse same-digit lanes into one atomic via match_any.
        for (int i = tid; i < S_; i += 1024) {
            unsigned int ky = key[i];
            bool pred = ((ky & pmask) == prefix);
            unsigned int d = (ky >> shift) & 255u;
            unsigned int m = __ballot_sync(0xffffffffu, pred);
            if (pred) {
                unsigned int grp = __match_any_sync(m, d);
                if ((unsigned)lane == (unsigned)(__ffs(grp) - 1))
                    atomicAdd(&hist[d], __popc(grp));
            }
        }
        __syncthreads();

        // suffix-sum over 256 bins, warp-shuffle based (bins reversed so an
        // inclusive forward scan over r = 255 - bin gives the suffix sum).
        // Warp w (w < 8) handles r in [32w, 32w+32).
        int svec = 0;
        if (wid < 8) {
            int bin = 255 - (wid * 32 + lane);
            svec = hist[bin];
#pragma unroll
            for (int off = 1; off < 32; off <<= 1) {
                int t = __shfl_up_sync(0xffffffffu, svec, off);
                if (lane >= off) svec += t;
            }
            if (lane == 31) wsum[wid] = svec;
        }
        __syncthreads();
        if (wid < 8) {
            // add totals of preceding warp-groups (at most 7 adds, uniform)
            int addv = 0;
#pragma unroll
            for (int g = 0; g < 7; g++)
                if (g < wid) addv += wsum[g];
            int sfx = svec + addv;                      // sum_{j>=bin} hist[j]
            // neighbor suffix (bin+1): previous r element's value
            int sprev = __shfl_up_sync(0xffffffffu, sfx, 1);
            if (lane == 0) sprev = (wid == 0) ? 0 : addv;
            // select unique digit: sfx >= kk_rem and sfx(bin+1) < kk_rem
            if (sfx >= kk_rem && sprev < kk_rem) {
                s_sel = 255 - (wid * 32 + lane);
                s_kk  = kk_rem - sprev;    // remaining to take from this bucket
            }
        }
        __syncthreads();
        prefix |= ((unsigned int)s_sel) << shift;
        pmask  |= 255u << shift;
        kk_rem = s_kk;
        __syncthreads();
    }
    const unsigned int T = prefix;   // k-th largest key value
    const int need = kk_rem;         // how many of the == T group to keep (>=1)

    // ---- stable tie-break: keep the `need` smallest-index elements == T ----
    // Blocked ownership: thread t owns elements [8t, 8t+8).
    const int base = tid * 8;
    unsigned int kv[8];
    int cnt = 0;
#pragma unroll
    for (int j = 0; j < 8; j++) {
        kv[j] = key[base + j];
        cnt += (kv[j] == T) ? 1 : 0;
    }

    // two-level inclusive scan of per-thread equal-counts
    int v = cnt;
#pragma unroll
    for (int off = 1; off < 32; off <<= 1) {
        int t = __shfl_up_sync(0xffffffffu, v, off);
        if (lane >= off) v += t;
    }
    if (lane == 31) wtot[wid] = v;
    __syncthreads();
    if (wid == 0) {
        int t = wtot[lane];
#pragma unroll
        for (int off = 1; off < 32; off <<= 1) {
            int u = __shfl_up_sync(0xffffffffu, t, off);
            if (lane >= off) t += u;
        }
        wtot[lane] = t;
    }
    __syncthreads();
    int run = (v - cnt) + (wid > 0 ? wtot[wid - 1] : 0);  // equals before my chunk

    // emit 8 floats (two float4 stores)
    float r0[8];
#pragma unroll
    for (int j = 0; j < 8; j++) {
        float kp = 0.0f;
        if (kv[j] > T) kp = 1.0f;
        else if (kv[j] == T) { kp = (run < need) ? 1.0f : 0.0f; run++; }
        r0[j] = kp;
    }
    float4* ro4 = reinterpret_cast<float4*>(ro + base);
    ro4[0] = make_float4(r0[0], r0[1], r0[2], r0[3]);
    ro4[1] = make_float4(r0[4], r0[5], r0[6], r0[7]);
}

extern "C" void kernel_launch(void* const* d_in, const int* in_sizes, int n_in,
                              void* d_out, int out_size)
{
    const float*        hidden = (const float*)d_in[0];
    const unsigned int* active = (const unsigned int*)d_in[1];
    const float*        w      = (const float*)d_in[2];
    const float*        bias   = (const float*)d_in[3];
    float*              out    = (float*)d_out;

    unsigned int* keys = nullptr;
    cudaGetSymbolAddress((void**)&keys, g_keys);

    score_kernel<<<NTOK / 8, 256>>>(hidden, active, w, bias, keys);
    select_kernel<<<B_, 1024>>>(keys, active, out);
}

// round 13
// speedup vs baseline: 1.1196x; 1.1196x over previous
#include <cuda_runtime.h>
#include <cuda_bf16.h>

// Problem: ExpertChoiceRouter  B=8, S=8192, D=1024, KEEP_RATIO=0.5
// R5 evidence: bool tensors promote to f32 (confirmed PASS in R11, 53.3us).
// R11 ncu: select_kernel = 13.2us latency-serial tail (8 blocks, issue 34%).
// This round: histogram moved into the HBM-bound score kernel (free), select
// reduced to suffix-scan + single emit pass + tiny exact in-bin ranking.

#define B_ 8
#define S_ 8192
#define D_ 1024
#define NTOK (B_ * S_)
#define HB   4096          // 12-bit histogram bins (key >> 20)
#define CAP  6144          // threshold-bin candidate capacity (typ. ~10 used)

// scratch (no cudaMalloc allowed). g_hist is self-cleaning: select_kernel
// zeroes it after reading, so every (graph-replayed) launch starts at zero.
__device__ unsigned int g_keys[NTOK];
__device__ int          g_hist[B_ * HB];

// ---------------------------------------------------------------------------
// Kernel 1: warp per token. key = flip(dot(hidden_row, w) + bias), masked.
// Also accumulates the per-row 12-bit histogram via one REDG per token.
// ---------------------------------------------------------------------------
__global__ __launch_bounds__(256) void score_kernel(
    const float* __restrict__ hidden,
    const unsigned int* __restrict__ active,   // f32/i32 words; nonzero = active
    const float* __restrict__ w,
    const float* __restrict__ bias,
    unsigned int* __restrict__ keys,
    int* __restrict__ hist)
{
    __shared__ float sw[D_];
    for (int i = threadIdx.x; i < D_; i += 256) sw[i] = w[i];
    __syncthreads();

    const int warp = threadIdx.x >> 5;
    const int lane = threadIdx.x & 31;
    const int token = blockIdx.x * 8 + warp;   // 8192 blocks * 8 warps = 65536

    const float4* __restrict__ row =
        reinterpret_cast<const float4*>(hidden + (size_t)token * D_);
    const float4* __restrict__ swv = reinterpret_cast<const float4*>(sw);

    float acc = 0.0f;
#pragma unroll
    for (int j = 0; j < 8; j++) {
        float4 v  = __ldcs(&row[lane + j * 32]);   // streaming: touched once
        float4 wv = swv[lane + j * 32];
        acc += v.x * wv.x + v.y * wv.y + v.z * wv.z + v.w * wv.w;
    }
#pragma unroll
    for (int o = 16; o; o >>= 1) acc += __shfl_xor_sync(0xffffffffu, acc, o);

    if (lane == 0) {
        float s = acc + bias[0];
        unsigned int u = __float_as_uint(s);
        // monotone map: larger float -> larger uint; active finite keys are > 0
        unsigned int kk = (u & 0x80000000u) ? ~u : (u | 0x80000000u);
        kk = (active[token] != 0u) ? kk : 0u;   // inactive -> 0 (bin 0)
        keys[token] = kk;
        atomicAdd(&hist[((token >> 13) << 12) | (kk >> 20)], 1);
    }
}

// ---------------------------------------------------------------------------
// Kernel 2: per-row top-k using the precomputed histogram.
// k = max(1, ceil(n_active * 0.5)) = (n_active + 1) / 2   (n_active > 0)
// Keys with (key>>20) > T12 are kept; within the threshold bin, exact ranking
// by (key desc, idx asc) keeps kk_rem elements (stable argsort tie-break).
// ---------------------------------------------------------------------------
__global__ __launch_bounds__(1024) void select_kernel(
    const unsigned int* __restrict__ keys,
    const unsigned int* __restrict__ active,
    int* __restrict__ hist,
    float* __restrict__ out)
{
    __shared__ unsigned int   ckey[CAP];       // 24 KB
    __shared__ unsigned short cidx[CAP];       // 12 KB
    __shared__ int wtot[32];
    __shared__ int s_nactive, s_cnt, s_t12, s_kk;

    const int tid  = threadIdx.x;
    const int lane = tid & 31;
    const int wid  = tid >> 5;
    const int row  = blockIdx.x;
    const unsigned int* rk = keys + row * S_;
    const unsigned int* ra = active + row * S_;
    float*              ro = out + row * S_;
    int*                rh = hist + row * HB;

    if (tid == 0) { s_nactive = 0; s_cnt = 0; }
    __syncthreads();

    // ---- n_active from mask (uint4) ----
    int my_active = 0;
    {
        const uint4* ra4 = reinterpret_cast<const uint4*>(ra);
        for (int i = tid; i < S_ / 4; i += 1024) {
            uint4 m = ra4[i];
            my_active += (m.x != 0u) + (m.y != 0u) + (m.z != 0u) + (m.w != 0u);
        }
    }
#pragma unroll
    for (int o = 16; o; o >>= 1) my_active += __shfl_xor_sync(0xffffffffu, my_active, o);
    if (lane == 0) atomicAdd(&s_nactive, my_active);

    // ---- read my 4 histogram bins (chunk c, from the TOP) and zero them ----
    // thread tid owns chunk c = 1023 - tid  -> bins [4c, 4c+4)
    const int c = 1023 - tid;
    int4 h4 = *reinterpret_cast<const int4*>(rh + 4 * c);
    *reinterpret_cast<int4*>(rh + 4 * c) = make_int4(0, 0, 0, 0);  // self-clean
    const int tsum = h4.x + h4.y + h4.z + h4.w;

    __syncthreads();
    const int n_active = s_nactive;
    if (n_active == 0) {
        float4 z = make_float4(0.f, 0.f, 0.f, 0.f);
        float4* ro4 = reinterpret_cast<float4*>(ro);
        for (int i = tid; i < S_ / 4; i += 1024) ro4[i] = z;
        return;
    }
    const int k = (n_active + 1) >> 1;        // ceil(n/2), >= 1, <= n_active

    // ---- two-level inclusive scan over tid of tsum (= suffix incl. my chunk) ----
    int v = tsum;
#pragma unroll
    for (int off = 1; off < 32; off <<= 1) {
        int t = __shfl_up_sync(0xffffffffu, v, off);
        if (lane >= off) v += t;
    }
    if (lane == 31) wtot[wid] = v;
    __syncthreads();
    if (wid == 0) {
        int t = wtot[lane];
#pragma unroll
        for (int off = 1; off < 32; off <<= 1) {
            int u = __shfl_up_sync(0xffffffffu, t, off);
            if (lane >= off) t += u;
        }
        wtot[lane] = t;
    }
    __syncthreads();
    const int sprev = (v - tsum) + (wid > 0 ? wtot[wid - 1] : 0);  // suffix above my chunk

    // crossing chunk: sprev < k <= sprev + tsum; exactly one thread fires
    if (sprev < k && sprev + tsum >= k) {
        int hh[4] = {h4.x, h4.y, h4.z, h4.w};
        int cum = sprev;                      // suffix strictly above bin j
#pragma unroll
        for (int j = 3; j >= 0; j--) {
            int nc = cum + hh[j];
            if (cum < k && nc >= k) { s_t12 = 4 * c + j; s_kk = k - cum; }
            cum = nc;
        }
    }
    __syncthreads();
    const unsigned int T12 = (unsigned int)s_t12;
    const int need = s_kk;                    // to take from the threshold bin

    // ---- emit pass: 8 elements per thread, straight from global ----
    const int base = tid * 8;
    uint4 k0 = *reinterpret_cast<const uint4*>(rk + base);
    uint4 k1 = *reinterpret_cast<const uint4*>(rk + base + 4);
    unsigned int kv[8] = {k0.x, k0.y, k0.z, k0.w, k1.x, k1.y, k1.z, k1.w};
    float r0[8];
#pragma unroll
    for (int j = 0; j < 8; j++) {
        unsigned int bin = kv[j] >> 20;
        float kp = 0.0f;
        if (bin > T12) kp = 1.0f;
        else if (bin == T12) {                // candidate: resolve after compaction
            int p = atomicAdd(&s_cnt, 1);
            if (p < CAP) { ckey[p] = kv[j]; cidx[p] = (unsigned short)(base + j); }
        }
        r0[j] = kp;
    }
    float4* ro4 = reinterpret_cast<float4*>(ro + base);
    ro4[0] = make_float4(r0[0], r0[1], r0[2], r0[3]);
    ro4[1] = make_float4(r0[4], r0[5], r0[6], r0[7]);
    __syncthreads();

    // ---- exact in-bin ranking: keep `need` by (key desc, idx asc) ----
    const int cnt = (s_cnt < CAP) ? s_cnt : CAP;
    for (int i = tid; i < cnt; i += 1024) {
        unsigned int ki = ckey[i];
        int ii = cidx[i];
        int rank = 0;
        for (int j = 0; j < cnt; j++) {
            unsigned int kj = ckey[j];
            rank += (kj > ki) || (kj == ki && (int)cidx[j] < ii);
        }
        if (rank < need) ro[ii] = 1.0f;
    }
}

extern "C" void kernel_launch(void* const* d_in, const int* in_sizes, int n_in,
                              void* d_out, int out_size)
{
    const float*        hidden = (const float*)d_in[0];
    const unsigned int* active = (const unsigned int*)d_in[1];
    const float*        w      = (const float*)d_in[2];
    const float*        bias   = (const float*)d_in[3];
    float*              out    = (float*)d_out;

    unsigned int* keys = nullptr;
    cudaGetSymbolAddress((void**)&keys, g_keys);
    int* hist = nullptr;
    cudaGetSymbolAddress((void**)&hist, g_hist);

    score_kernel<<<NTOK / 8, 256>>>(hidden, active, w, bias, keys, hist);
    select_kernel<<<B_, 1024>>>(keys, active, hist, out);
}